// round 13
// baseline (speedup 1.0000x reference)
#include <cuda_runtime.h>
#include <cuda_bf16.h>
#include <cstdint>

#define NB 2
#define NH 16
#define SS 2048
#define DK 64
#define DM 1024
#define NBH (NB*NH)     // 32
#define MROWS (NB*SS)   // 4096

// ---------------- scratch (allocation-free rule) ----------------
__device__ __align__(256) float g_wt[4][DM*DM];         // W^T (K-major)
__device__ __align__(256) uint16_t g_qh_h[NBH*SS*DK];   // bf16 hi [bh][s][dk]
__device__ __align__(256) uint16_t g_qh_l[NBH*SS*DK];   // bf16 lo
__device__ __align__(256) uint16_t g_kh_h[NBH*SS*DK];
__device__ __align__(256) uint16_t g_kh_l[NBH*SS*DK];
__device__ __align__(256) uint16_t g_vt_h[NBH*DK*SS];   // [bh][dk][s]
__device__ __align__(256) uint16_t g_vt_l[NBH*DK*SS];
__device__ __align__(256) float g_ctx[(size_t)MROWS*DM];
__device__ __align__(256) float2 g_stats[NBH*SS];       // (max2, sum) log2 domain

#define EP_F32 0
#define EP_QK  1
#define EP_VT  2

__device__ __forceinline__ uint32_t split2(float a, float b, uint32_t& lo) {
    __nv_bfloat162 h = __floats2bfloat162_rn(a, b);
    __nv_bfloat162 l = __floats2bfloat162_rn(a - __low2float(h), b - __high2float(h));
    lo = reinterpret_cast<uint32_t&>(l);
    return reinterpret_cast<uint32_t&>(h);
}

__device__ __forceinline__ void mma16816(float* c,
                                         uint32_t a0, uint32_t a1, uint32_t a2, uint32_t a3,
                                         uint32_t b0, uint32_t b1) {
    asm volatile(
        "mma.sync.aligned.m16n8k16.row.col.f32.bf16.bf16.f32 "
        "{%0,%1,%2,%3}, {%4,%5,%6,%7}, {%8,%9}, {%0,%1,%2,%3};"
        : "+f"(c[0]), "+f"(c[1]), "+f"(c[2]), "+f"(c[3])
        : "r"(a0), "r"(a1), "r"(a2), "r"(a3), "r"(b0), "r"(b1));
}

__device__ __forceinline__ void ldsm_x4(uint32_t& r0, uint32_t& r1,
                                        uint32_t& r2, uint32_t& r3, uint32_t a) {
    asm volatile("ldmatrix.sync.aligned.m8n8.x4.shared.b16 {%0,%1,%2,%3}, [%4];"
        : "=r"(r0), "=r"(r1), "=r"(r2), "=r"(r3) : "r"(a));
}

__device__ __forceinline__ float ex2(float x) {
    float y;
    asm("ex2.approx.f32 %0, %1;" : "=f"(y) : "f"(x));
    return y;
}

__device__ __forceinline__ void stcs2(float* p, float x, float y) {
    asm volatile("st.global.cs.v2.f32 [%0], {%1, %2};" :: "l"(p), "f"(x), "f"(y) : "memory");
}

__device__ __forceinline__ void cpa16(uint32_t dst, const void* src) {
    asm volatile("cp.async.cg.shared.global [%0], [%1], 16;" :: "r"(dst), "l"(src) : "memory");
}
#define CP_COMMIT() asm volatile("cp.async.commit_group;" ::: "memory")
#define CP_WAIT0()  asm volatile("cp.async.wait_group 0;" ::: "memory")

#define LDSTRIDE 40
#define ASZB (128 * LDSTRIDE * 2)

__device__ __forceinline__ void split_store(char* dst_h, char* dst_l, float4 v) {
    uint32_t l0, l1;
    uint32_t h0 = split2(v.x, v.y, l0);
    uint32_t h1 = split2(v.z, v.w, l1);
    *(uint2*)dst_h = make_uint2(h0, h1);
    *(uint2*)dst_l = make_uint2(l0, l1);
}

// ---------------------------------------------------------------------------
// HMMA bf16-split GEMM body, 512 threads / 16 warps. C tile 128x128, BK=32.
// Warp tile 32x32: wm = wid&3 (row strip), wn = wid>>2 (col strip).
// ---------------------------------------------------------------------------
__device__ __forceinline__ void gemm_hmma_body(
    int m0, int n0,
    const float* __restrict__ A, int lda,
    const float* __restrict__ B, int ldb, int K,
    const float* __restrict__ bias,
    float* __restrict__ out, int ldo,
    uint16_t* __restrict__ oh, uint16_t* __restrict__ ol,
    float scale, int mode, char* sm)
{
    constexpr int BN = 128, NI = 4, NP = 2;
    constexpr int BSZB = BN * LDSTRIDE * 2;
    constexpr int BHOFF = 2 * ASZB;
    constexpr int BUFSTR = 2 * ASZB + 2 * BSZB;

    const uint32_t smu = (uint32_t)__cvta_generic_to_shared(sm);

    const int tid  = threadIdx.x;
    const int wid  = tid >> 5;
    const int lane = tid & 31;
    const int g = lane >> 2;
    const int t = lane & 3;
    const int wm = wid & 3;
    const int wn = wid >> 2;

    const int lmat = lane >> 3;
    const int lr   = lane & 7;
    const int a_row_off = (lmat & 1) * 8 + lr;
    const int a_k_off   = (lmat >> 1) * 8;
    const int b_ni_off  = (lmat >> 1);
    const int b_k_off   = (lmat & 1) * 8;

    // loaders: 4 threads per row, 8 floats each
    const int r  = tid >> 2;
    const int q4 = tid & 3;
    const float* Ap = A + (size_t)(m0 + r) * lda + q4 * 8;
    const float* Bp = B + (size_t)(n0 + r) * ldb + q4 * 8;

    float acc[2][NI][4];
    #pragma unroll
    for (int mi = 0; mi < 2; mi++)
        #pragma unroll
        for (int ni = 0; ni < NI; ni++)
            #pragma unroll
            for (int c = 0; c < 4; c++) acc[mi][ni][c] = 0.f;

    const int nchunk = K >> 5;

    {
        char* bh = sm + (r * LDSTRIDE + q4 * 8) * 2;
        split_store(bh,     bh + ASZB,     *(const float4*)(Ap));
        split_store(bh + 8, bh + ASZB + 8, *(const float4*)(Ap + 4));
        char* bb = sm + BHOFF + (r * LDSTRIDE + q4 * 8) * 2;
        split_store(bb,     bb + BSZB,     *(const float4*)(Bp));
        split_store(bb + 8, bb + BSZB + 8, *(const float4*)(Bp + 4));
    }
    __syncthreads();

    for (int c = 0; c < nchunk; c++) {
        const int buf = c & 1;
        const bool more = (c + 1 < nchunk);

        float4 pa[2], pb[2];
        if (more) {
            const int k0 = (c + 1) << 5;
            pa[0] = *(const float4*)(Ap + k0);
            pa[1] = *(const float4*)(Ap + k0 + 4);
            pb[0] = *(const float4*)(Bp + k0);
            pb[1] = *(const float4*)(Bp + k0 + 4);
        }

        const uint32_t base = smu + buf * BUFSTR;
        #pragma unroll
        for (int kk = 0; kk < 32; kk += 16) {
            uint32_t bfh[NI][2], bfl[NI][2];
            #pragma unroll
            for (int p = 0; p < NP; p++) {
                const int ni = p * 2 + b_ni_off;
                const int n = wn * 32 + ni * 8 + lr;
                const uint32_t ab = base + BHOFF + (uint32_t)(n * LDSTRIDE + kk + b_k_off) * 2;
                ldsm_x4(bfh[p*2][0], bfh[p*2][1], bfh[p*2+1][0], bfh[p*2+1][1], ab);
                ldsm_x4(bfl[p*2][0], bfl[p*2][1], bfl[p*2+1][0], bfl[p*2+1][1], ab + BSZB);
            }
            #pragma unroll
            for (int mi = 0; mi < 2; mi++) {
                const int row = wm * 32 + mi * 16 + a_row_off;
                const uint32_t aa = base + (uint32_t)(row * LDSTRIDE + kk + a_k_off) * 2;
                uint32_t ah0, ah1, ah2, ah3, al0, al1, al2, al3;
                ldsm_x4(ah0, ah1, ah2, ah3, aa);
                ldsm_x4(al0, al1, al2, al3, aa + ASZB);
                #pragma unroll
                for (int np = 0; np < NI / 2; np++) {
                    float* c0 = acc[mi][np*2];
                    float* c1 = acc[mi][np*2+1];
                    mma16816(c0, ah0, ah1, ah2, ah3, bfh[np*2][0],   bfh[np*2][1]);
                    mma16816(c1, ah0, ah1, ah2, ah3, bfh[np*2+1][0], bfh[np*2+1][1]);
                    mma16816(c0, ah0, ah1, ah2, ah3, bfl[np*2][0],   bfl[np*2][1]);
                    mma16816(c1, ah0, ah1, ah2, ah3, bfl[np*2+1][0], bfl[np*2+1][1]);
                    mma16816(c0, al0, al1, al2, al3, bfh[np*2][0],   bfh[np*2][1]);
                    mma16816(c1, al0, al1, al2, al3, bfh[np*2+1][0], bfh[np*2+1][1]);
                }
            }
        }

        if (more) {
            __syncthreads();
            char* bh = sm + (buf ^ 1) * BUFSTR + (r * LDSTRIDE + q4 * 8) * 2;
            split_store(bh,     bh + ASZB,     pa[0]);
            split_store(bh + 8, bh + ASZB + 8, pa[1]);
            char* bb = sm + (buf ^ 1) * BUFSTR + BHOFF + (r * LDSTRIDE + q4 * 8) * 2;
            split_store(bb,     bb + BSZB,     pb[0]);
            split_store(bb + 8, bb + BSZB + 8, pb[1]);
            __syncthreads();
        }
    }

    const bool hasb = (bias != nullptr);
    #pragma unroll
    for (int mi = 0; mi < 2; mi++) {
        #pragma unroll
        for (int ni = 0; ni < NI; ni++) {
            const int row0 = m0 + wm * 32 + mi * 16 + g;
            const int row1 = row0 + 8;
            const int col  = n0 + wn * 32 + ni * 8 + 2 * t;
            float b0 = hasb ? bias[col]     : 0.f;
            float b1 = hasb ? bias[col + 1] : 0.f;
            float v0 = acc[mi][ni][0] * scale + b0;
            float v1 = acc[mi][ni][1] * scale + b1;
            float v2 = acc[mi][ni][2] * scale + b0;
            float v3 = acc[mi][ni][3] * scale + b1;
            if (mode == EP_F32) {
                *(float2*)(out + (size_t)row0 * ldo + col) = make_float2(v0, v1);
                *(float2*)(out + (size_t)row1 * ldo + col) = make_float2(v2, v3);
            } else if (mode == EP_QK) {
                int h = col >> 6, dk = col & 63;
                int b_0 = row0 >> 11, s_0 = row0 & (SS - 1);
                int b_1 = row1 >> 11, s_1 = row1 & (SS - 1);
                uint32_t l01, l23;
                uint32_t h01 = split2(v0, v1, l01);
                uint32_t h23 = split2(v2, v3, l23);
                size_t i0 = ((size_t)(b_0 * NH + h) * SS + s_0) * DK + dk;
                size_t i1 = ((size_t)(b_1 * NH + h) * SS + s_1) * DK + dk;
                *(uint32_t*)(oh + i0) = h01; *(uint32_t*)(ol + i0) = l01;
                *(uint32_t*)(oh + i1) = h23; *(uint32_t*)(ol + i1) = l23;
            } else { // EP_VT: transposed singles
                int h = col >> 6, dk = col & 63;
                int b_0 = row0 >> 11, s_0 = row0 & (SS - 1);
                int b_1 = row1 >> 11, s_1 = row1 & (SS - 1);
                float vv[4] = {v0, v1, v2, v3};
                #pragma unroll
                for (int e = 0; e < 4; e++) {
                    int dkk = dk + (e & 1);
                    int ss  = (e < 2) ? s_0 : s_1;
                    int bb0 = (e < 2) ? b_0 : b_1;
                    __nv_bfloat16 hb = __float2bfloat16(vv[e]);
                    __nv_bfloat16 lb = __float2bfloat16(vv[e] - __bfloat162float(hb));
                    size_t idx = ((size_t)(bb0 * NH + h) * DK + dkk) * SS + ss;
                    oh[idx] = reinterpret_cast<uint16_t&>(hb);
                    ol[idx] = reinterpret_cast<uint16_t&>(lb);
                }
            }
        }
    }
}

__global__ void __launch_bounds__(512)
qkv_proj_kernel(const float* __restrict__ q, const float* __restrict__ k,
                const float* __restrict__ v,
                const float* __restrict__ wtq, const float* __restrict__ wtk,
                const float* __restrict__ wtv,
                const float* __restrict__ bq, const float* __restrict__ bk,
                const float* __restrict__ bv)
{
    extern __shared__ char sm[];
    const int z = blockIdx.z;
    const float* A = (z == 0) ? q : (z == 1) ? k : v;
    const float* B = (z == 0) ? wtq : (z == 1) ? wtk : wtv;
    const float* bias = (z == 0) ? bq : (z == 1) ? bk : bv;
    uint16_t* oh = (z == 0) ? g_qh_h : (z == 1) ? g_kh_h : g_vt_h;
    uint16_t* ol = (z == 0) ? g_qh_l : (z == 1) ? g_kh_l : g_vt_l;
    const int mode = (z == 2) ? EP_VT : EP_QK;
    gemm_hmma_body(blockIdx.y * 128, blockIdx.x * 128,
                   A, DM, B, DM, DM, bias, nullptr, 0, oh, ol, 1.f, mode, sm);
}

__global__ void __launch_bounds__(512)
out_proj_kernel(const float* __restrict__ A, const float* __restrict__ B,
                const float* __restrict__ bias, float* __restrict__ out)
{
    extern __shared__ char sm[];
    gemm_hmma_body(blockIdx.y * 128, blockIdx.x * 128,
                   A, DM, B, DM, DM, bias, out, DM, nullptr, nullptr, 1.f, EP_F32, sm);
}

// ===========================================================================
// Fused attention, 512 threads, cp.async double-buffered K/V.
// warp = (rowgrp 0-7, nhalf 0-1): 16 rows x 64 chunk-cols each.
// ===========================================================================
#define QSTR 144
#define VSTR 272
#define QHSZ 18432
#define VHSZ 17408
#define KOFF 36864
#define S1_BUF 36864
#define S2_BUF 71680
#define S1_SMEM (KOFF + 2*S1_BUF)
#define S2_SMEM (KOFF + 2*S2_BUF)

#define S2LOG 0.1803368801111204f  // 0.125 * log2(e)

// ---- pass 1: online softmax stats, 512 threads, N-split ----
__global__ void __launch_bounds__(512) attn_stats_kernel()
{
    extern __shared__ char sm[];
    const uint32_t smu = (uint32_t)__cvta_generic_to_shared(sm);
    const int tid = threadIdx.x;
    const int w = tid >> 5;
    const int rowgrp = w >> 1;
    const int nhalf  = w & 1;
    const int lane = tid & 31;
    const int g = lane >> 2, t = lane & 3;
    const int lmat = lane >> 3, lr = lane & 7;
    const int a_row_off = (lmat & 1) * 8 + lr;
    const int a_k_off   = (lmat >> 1) * 8;
    const int b_ni_off  = (lmat >> 1);
    const int b_k_off   = (lmat & 1) * 8;

    const int m0 = blockIdx.x * 128;
    const int bh = blockIdx.y;

    const int r  = tid >> 2, q4 = tid & 3;
    const uint16_t* Qh = g_qh_h + ((size_t)bh * SS + m0 + r) * DK + q4 * 16;
    const uint16_t* Ql = g_qh_l + ((size_t)bh * SS + m0 + r) * DK + q4 * 16;
    const uint16_t* Kh = g_kh_h + ((size_t)bh * SS + r) * DK + q4 * 16;
    const uint16_t* Kl = g_kh_l + ((size_t)bh * SS + r) * DK + q4 * 16;
    const uint32_t rowdst = (uint32_t)(r * QSTR + q4 * 32);

    cpa16(smu + rowdst,             Qh);   cpa16(smu + rowdst + 16,           Qh + 8);
    cpa16(smu + rowdst + QHSZ,      Ql);   cpa16(smu + rowdst + QHSZ + 16,    Ql + 8);
    cpa16(smu + KOFF + rowdst,      Kh);   cpa16(smu + KOFF + rowdst + 16,    Kh + 8);
    cpa16(smu + KOFF + rowdst+QHSZ, Kl);   cpa16(smu + KOFF + rowdst+QHSZ+16, Kl + 8);
    CP_COMMIT();

    uint32_t aqh[4][4], aql[4][4];
    float m[2] = {-1e30f, -1e30f}, s[2] = {0.f, 0.f};

    for (int j = 0; j < 16; j++) {
        CP_WAIT0();
        __syncthreads();
        if (j == 0) {
            #pragma unroll
            for (int kk = 0; kk < 4; kk++) {
                const int row = rowgrp * 16 + a_row_off;
                const uint32_t aa = smu + (uint32_t)(row * QSTR) + (kk * 16 + a_k_off) * 2;
                ldsm_x4(aqh[kk][0], aqh[kk][1], aqh[kk][2], aqh[kk][3], aa);
                ldsm_x4(aql[kk][0], aql[kk][1], aql[kk][2], aql[kk][3], aa + QHSZ);
            }
        }
        if (j + 1 < 16) {
            const uint32_t d = smu + KOFF + ((j + 1) & 1) * S1_BUF;
            const uint16_t* kh2 = Kh + (size_t)(j + 1) * 128 * DK;
            const uint16_t* kl2 = Kl + (size_t)(j + 1) * 128 * DK;
            cpa16(d + rowdst,          kh2); cpa16(d + rowdst + 16,          kh2 + 8);
            cpa16(d + rowdst + QHSZ,   kl2); cpa16(d + rowdst + QHSZ + 16,   kl2 + 8);
            CP_COMMIT();
        }

        const uint32_t kbase = smu + KOFF + (j & 1) * S1_BUF;
        float acc[8][4];
        #pragma unroll
        for (int ni = 0; ni < 8; ni++)
            #pragma unroll
            for (int c = 0; c < 4; c++) acc[ni][c] = 0.f;

        #pragma unroll
        for (int kk = 0; kk < 4; kk++) {
            #pragma unroll
            for (int p = 0; p < 4; p++) {
                const int ni = p * 2 + b_ni_off;
                const int n = nhalf * 64 + ni * 8 + lr;
                const uint32_t ab = kbase + (uint32_t)(n * QSTR) + (kk * 16 + b_k_off) * 2;
                uint32_t bh0, bh1, bh2, bh3, bl0, bl1, bl2, bl3;
                ldsm_x4(bh0, bh1, bh2, bh3, ab);
                ldsm_x4(bl0, bl1, bl2, bl3, ab + QHSZ);
                float* c0 = acc[p*2];
                float* c1 = acc[p*2+1];
                mma16816(c0, aqh[kk][0], aqh[kk][1], aqh[kk][2], aqh[kk][3], bh0, bh1);
                mma16816(c1, aqh[kk][0], aqh[kk][1], aqh[kk][2], aqh[kk][3], bh2, bh3);
                mma16816(c0, aqh[kk][0], aqh[kk][1], aqh[kk][2], aqh[kk][3], bl0, bl1);
                mma16816(c1, aqh[kk][0], aqh[kk][1], aqh[kk][2], aqh[kk][3], bl2, bl3);
                mma16816(c0, aql[kk][0], aql[kk][1], aql[kk][2], aql[kk][3], bh0, bh1);
                mma16816(c1, aql[kk][0], aql[kk][1], aql[kk][2], aql[kk][3], bh2, bh3);
            }
        }

        #pragma unroll
        for (int h2 = 0; h2 < 2; h2++) {
            float cm = -1e30f;
            #pragma unroll
            for (int ni = 0; ni < 8; ni++)
                cm = fmaxf(cm, fmaxf(acc[ni][h2*2], acc[ni][h2*2+1]));
            cm *= S2LOG;
            cm = fmaxf(cm, __shfl_xor_sync(0xffffffffu, cm, 1));
            cm = fmaxf(cm, __shfl_xor_sync(0xffffffffu, cm, 2));
            float mn = fmaxf(m[h2], cm);
            float sum = 0.f;
            #pragma unroll
            for (int ni = 0; ni < 8; ni++) {
                sum += ex2(fmaf(acc[ni][h2*2],   S2LOG, -mn));
                sum += ex2(fmaf(acc[ni][h2*2+1], S2LOG, -mn));
            }
            sum += __shfl_xor_sync(0xffffffffu, sum, 1);
            sum += __shfl_xor_sync(0xffffffffu, sum, 2);
            s[h2] = s[h2] * ex2(m[h2] - mn) + sum;
            m[h2] = mn;
        }
    }

    // cross-nhalf merge via smem (buffers dead now)
    __syncthreads();
    float2* red = (float2*)sm;  // [128 rows][2 halves]
    if (t == 0) {
        red[(rowgrp * 16 + g) * 2 + nhalf]       = make_float2(m[0], s[0]);
        red[(rowgrp * 16 + g + 8) * 2 + nhalf]   = make_float2(m[1], s[1]);
    }
    __syncthreads();
    if (nhalf == 0 && t == 0) {
        #pragma unroll
        for (int h2 = 0; h2 < 2; h2++) {
            const int rr = rowgrp * 16 + g + h2 * 8;
            float2 a = red[rr * 2 + 0];
            float2 b = red[rr * 2 + 1];
            float mn = fmaxf(a.x, b.x);
            float ss = a.y * ex2(a.x - mn) + b.y * ex2(b.x - mn);
            g_stats[(size_t)bh * SS + m0 + rr] = make_float2(mn, ss);
        }
    }
}

// ---- pass 2: 512 threads, weights + PV (unchanged from R12) ----
__global__ void __launch_bounds__(512) attn_wv_kernel(float* __restrict__ attn)
{
    extern __shared__ char sm[];
    const uint32_t smu = (uint32_t)__cvta_generic_to_shared(sm);
    const int tid = threadIdx.x;
    const int w = tid >> 5;
    const int rowgrp = w >> 1;
    const int nhalf  = w & 1;
    const int lane = tid & 31;
    const int g = lane >> 2, t = lane & 3;
    const int lmat = lane >> 3, lr = lane & 7;
    const int a_row_off = (lmat & 1) * 8 + lr;
    const int a_k_off   = (lmat >> 1) * 8;
    const int b_ni_off  = (lmat >> 1);
    const int b_k_off   = (lmat & 1) * 8;

    const int m0 = blockIdx.x * 128;
    const int bh = blockIdx.y;
    const int bb = bh >> 4, hh = bh & 15;
    float* attn_b = attn + (size_t)bh * SS * SS;

    const int r  = tid >> 2, q4 = tid & 3;
    const uint16_t* Qh = g_qh_h + ((size_t)bh * SS + m0 + r) * DK + q4 * 16;
    const uint16_t* Ql = g_qh_l + ((size_t)bh * SS + m0 + r) * DK + q4 * 16;
    const uint16_t* Kh = g_kh_h + ((size_t)bh * SS + r) * DK + q4 * 16;
    const uint16_t* Kl = g_kh_l + ((size_t)bh * SS + r) * DK + q4 * 16;
    const uint32_t rowdst = (uint32_t)(r * QSTR + q4 * 32);

    const int vr = tid >> 3, v8 = tid & 7;
    const uint16_t* Vh = g_vt_h + ((size_t)bh * DK + vr) * SS + v8 * 16;
    const uint16_t* Vl = g_vt_l + ((size_t)bh * DK + vr) * SS + v8 * 16;
    const uint32_t vrowdst = (uint32_t)(vr * VSTR + v8 * 32);

    cpa16(smu + rowdst,             Qh);     cpa16(smu + rowdst + 16,             Qh + 8);
    cpa16(smu + rowdst + QHSZ,      Ql);     cpa16(smu + rowdst + QHSZ + 16,      Ql + 8);
    cpa16(smu + KOFF + rowdst,      Kh);     cpa16(smu + KOFF + rowdst + 16,      Kh + 8);
    cpa16(smu + KOFF + rowdst+QHSZ, Kl);     cpa16(smu + KOFF + rowdst+QHSZ+16,   Kl + 8);
    {
        const uint32_t vd = smu + KOFF + 2*QHSZ + vrowdst;
        cpa16(vd, Vh);              cpa16(vd + 16, Vh + 8);
        cpa16(vd + VHSZ, Vl);       cpa16(vd + VHSZ + 16, Vl + 8);
    }
    CP_COMMIT();

    const int row0 = m0 + rowgrp * 16 + g;
    float2 st0 = g_stats[(size_t)bh * SS + row0];
    float2 st1 = g_stats[(size_t)bh * SS + row0 + 8];
    const float mm0 = st0.x, is0 = 1.f / st0.y;
    const float mm1 = st1.x, is1 = 1.f / st1.y;

    float ctx[8][4];
    #pragma unroll
    for (int ni = 0; ni < 8; ni++)
        #pragma unroll
        for (int c = 0; c < 4; c++) ctx[ni][c] = 0.f;

    uint32_t aqh[4][4], aql[4][4];

    for (int j = 0; j < 16; j++) {
        CP_WAIT0();
        __syncthreads();
        if (j == 0) {
            #pragma unroll
            for (int kk = 0; kk < 4; kk++) {
                const int row = rowgrp * 16 + a_row_off;
                const uint32_t aa = smu + (uint32_t)(row * QSTR) + (kk * 16 + a_k_off) * 2;
                ldsm_x4(aqh[kk][0], aqh[kk][1], aqh[kk][2], aqh[kk][3], aa);
                ldsm_x4(aql[kk][0], aql[kk][1], aql[kk][2], aql[kk][3], aa + QHSZ);
            }
        }
        if (j + 1 < 16) {
            const uint32_t bb2 = smu + KOFF + ((j + 1) & 1) * S2_BUF;
            const uint16_t* kh2 = Kh + (size_t)(j + 1) * 128 * DK;
            const uint16_t* kl2 = Kl + (size_t)(j + 1) * 128 * DK;
            cpa16(bb2 + rowdst,           kh2); cpa16(bb2 + rowdst + 16,           kh2 + 8);
            cpa16(bb2 + rowdst + QHSZ,    kl2); cpa16(bb2 + rowdst + QHSZ + 16,    kl2 + 8);
            const uint32_t vd = bb2 + 2*QHSZ + vrowdst;
            const uint16_t* vh2 = Vh + (j + 1) * 128;
            const uint16_t* vl2 = Vl + (j + 1) * 128;
            cpa16(vd, vh2);         cpa16(vd + 16, vh2 + 8);
            cpa16(vd + VHSZ, vl2);  cpa16(vd + VHSZ + 16, vl2 + 8);
            CP_COMMIT();
        }

        const uint32_t kbase = smu + KOFF + (j & 1) * S2_BUF;
        const uint32_t vbase = kbase + 2*QHSZ;

        float acc[8][4];
        #pragma unroll
        for (int ni = 0; ni < 8; ni++)
            #pragma unroll
            for (int c = 0; c < 4; c++) acc[ni][c] = 0.f;

        #pragma unroll
        for (int kk = 0; kk < 4; kk++) {
            #pragma unroll
            for (int p = 0; p < 4; p++) {
                const int ni = p * 2 + b_ni_off;
                const int n = nhalf * 64 + ni * 8 + lr;
                const uint32_t ab = kbase + (uint32_t)(n * QSTR) + (kk * 16 + b_k_off) * 2;
                uint32_t bh0, bh1, bh2, bh3, bl0, bl1, bl2, bl3;
                ldsm_x4(bh0, bh1, bh2, bh3, ab);
                ldsm_x4(bl0, bl1, bl2, bl3, ab + QHSZ);
                float* c0 = acc[p*2];
                float* c1 = acc[p*2+1];
                mma16816(c0, aqh[kk][0], aqh[kk][1], aqh[kk][2], aqh[kk][3], bh0, bh1);
                mma16816(c1, aqh[kk][0], aqh[kk][1], aqh[kk][2], aqh[kk][3], bh2, bh3);
                mma16816(c0, aqh[kk][0], aqh[kk][1], aqh[kk][2], aqh[kk][3], bl0, bl1);
                mma16816(c1, aqh[kk][0], aqh[kk][1], aqh[kk][2], aqh[kk][3], bl2, bl3);
                mma16816(c0, aql[kk][0], aql[kk][1], aql[kk][2], aql[kk][3], bh0, bh1);
                mma16816(c1, aql[kk][0], aql[kk][1], aql[kk][2], aql[kk][3], bh2, bh3);
            }
        }

        #pragma unroll
        for (int ni = 0; ni < 8; ni++) {
            acc[ni][0] = ex2(fmaf(acc[ni][0], S2LOG, -mm0)) * is0;
            acc[ni][1] = ex2(fmaf(acc[ni][1], S2LOG, -mm0)) * is0;
            acc[ni][2] = ex2(fmaf(acc[ni][2], S2LOG, -mm1)) * is1;
            acc[ni][3] = ex2(fmaf(acc[ni][3], S2LOG, -mm1)) * is1;
        }

        {
            float* p0 = attn_b + (size_t)row0 * SS + j * 128 + nhalf * 64 + 2 * t;
            float* p1 = attn_b + (size_t)(row0 + 8) * SS + j * 128 + nhalf * 64 + 2 * t;
            #pragma unroll
            for (int ni = 0; ni < 8; ni++) {
                stcs2(p0 + ni * 8, acc[ni][0], acc[ni][1]);
                stcs2(p1 + ni * 8, acc[ni][2], acc[ni][3]);
            }
        }

        #pragma unroll
        for (int u = 0; u < 4; u++) {
            uint32_t al0, al1, al2, al3;
            uint32_t ah0 = split2(acc[2*u][0],   acc[2*u][1],   al0);
            uint32_t ah1 = split2(acc[2*u][2],   acc[2*u][3],   al1);
            uint32_t ah2 = split2(acc[2*u+1][0], acc[2*u+1][1], al2);
            uint32_t ah3 = split2(acc[2*u+1][2], acc[2*u+1][3], al3);
            #pragma unroll
            for (int p = 0; p < 4; p++) {
                const int nv = (p * 2 + b_ni_off) * 8 + lr;
                const uint32_t ab = vbase + (uint32_t)(nv * VSTR)
                                  + (nhalf * 64 + u * 16 + b_k_off) * 2;
                uint32_t vh0, vh1, vh2, vh3, vl0, vl1, vl2, vl3;
                ldsm_x4(vh0, vh1, vh2, vh3, ab);
                ldsm_x4(vl0, vl1, vl2, vl3, ab + VHSZ);
                float* c0 = ctx[p*2];
                float* c1 = ctx[p*2+1];
                mma16816(c0, ah0, ah1, ah2, ah3, vh0, vh1);
                mma16816(c1, ah0, ah1, ah2, ah3, vh2, vh3);
                mma16816(c0, ah0, ah1, ah2, ah3, vl0, vl1);
                mma16816(c1, ah0, ah1, ah2, ah3, vl2, vl3);
                mma16816(c0, al0, al1, al2, al3, vh0, vh1);
                mma16816(c1, al0, al1, al2, al3, vh2, vh3);
            }
        }
    }

    __syncthreads();
    float* red = (float*)sm;
    if (nhalf == 1) {
        #pragma unroll
        for (int ni = 0; ni < 8; ni++) {
            const int dk = ni * 8 + 2 * t;
            *(float2*)&red[(rowgrp * 16 + g) * 64 + dk]     = make_float2(ctx[ni][0], ctx[ni][1]);
            *(float2*)&red[(rowgrp * 16 + g + 8) * 64 + dk] = make_float2(ctx[ni][2], ctx[ni][3]);
        }
    }
    __syncthreads();
    if (nhalf == 0) {
        #pragma unroll
        for (int ni = 0; ni < 8; ni++) {
            const int dk = ni * 8 + 2 * t;
            float2 o0 = *(float2*)&red[(rowgrp * 16 + g) * 64 + dk];
            float2 o1 = *(float2*)&red[(rowgrp * 16 + g + 8) * 64 + dk];
            float* p0 = g_ctx + ((size_t)(bb * SS) + row0) * DM + hh * DK + dk;
            float* p1 = g_ctx + ((size_t)(bb * SS) + row0 + 8) * DM + hh * DK + dk;
            *(float2*)p0 = make_float2(ctx[ni][0] + o0.x, ctx[ni][1] + o0.y);
            *(float2*)p1 = make_float2(ctx[ni][2] + o1.x, ctx[ni][3] + o1.y);
        }
    }
}

// ---------------------------------------------------------------------------
__global__ void transpose4_kernel(const float* __restrict__ s0, const float* __restrict__ s1,
                                  const float* __restrict__ s2, const float* __restrict__ s3,
                                  float* __restrict__ d0, float* __restrict__ d1,
                                  float* __restrict__ d2, float* __restrict__ d3)
{
    __shared__ float tile[32][33];
    const int z = blockIdx.z;
    const float* src = (z == 0) ? s0 : (z == 1) ? s1 : (z == 2) ? s2 : s3;
    float* dst = (z == 0) ? d0 : (z == 1) ? d1 : (z == 2) ? d2 : d3;
    int bx = blockIdx.x * 32, by = blockIdx.y * 32;
    int tx = threadIdx.x, ty = threadIdx.y;
    #pragma unroll
    for (int i = 0; i < 32; i += 8)
        tile[ty + i][tx] = src[(size_t)(by + ty + i) * DM + bx + tx];
    __syncthreads();
    #pragma unroll
    for (int i = 0; i < 32; i += 8)
        dst[(size_t)(bx + ty + i) * DM + by + tx] = tile[tx][ty + i];
}

// ---------------------------------------------------------------------------
extern "C" void kernel_launch(void* const* d_in, const int* in_sizes, int n_in,
                              void* d_out, int out_size)
{
    const float* q  = (const float*)d_in[0];
    const float* k  = (const float*)d_in[1];
    const float* v  = (const float*)d_in[2];
    const float* Wq = (const float*)d_in[3];
    const float* bq = (const float*)d_in[4];
    const float* Wk = (const float*)d_in[5];
    const float* bk = (const float*)d_in[6];
    const float* Wv = (const float*)d_in[7];
    const float* bv = (const float*)d_in[8];
    const float* Wo = (const float*)d_in[9];
    const float* bo = (const float*)d_in[10];

    float* out  = (float*)d_out;
    float* attn = out + (size_t)MROWS * DM;

    void *wt, *ctx;
    cudaGetSymbolAddress(&wt,  g_wt);
    cudaGetSymbolAddress(&ctx, g_ctx);
    float* wtq = (float*)wt;
    float* wtk = wtq + (size_t)DM*DM;
    float* wtv = wtk + (size_t)DM*DM;
    float* wto = wtv + (size_t)DM*DM;

    const int smem128 = 2 * (2*ASZB + 2*128*LDSTRIDE*2);  // 81920
    cudaFuncSetAttribute(qkv_proj_kernel,
                         cudaFuncAttributeMaxDynamicSharedMemorySize, smem128);
    cudaFuncSetAttribute(out_proj_kernel,
                         cudaFuncAttributeMaxDynamicSharedMemorySize, smem128);
    cudaFuncSetAttribute(attn_stats_kernel,
                         cudaFuncAttributeMaxDynamicSharedMemorySize, S1_SMEM);
    cudaFuncSetAttribute(attn_wv_kernel,
                         cudaFuncAttributeMaxDynamicSharedMemorySize, S2_SMEM);

    transpose4_kernel<<<dim3(32, 32, 4), dim3(32, 8)>>>(Wq, Wk, Wv, Wo,
                                                        wtq, wtk, wtv, wto);

    qkv_proj_kernel<<<dim3(8, 32, 3), 512, smem128>>>(
        q, k, v, wtq, wtk, wtv, bq, bk, bv);

    attn_stats_kernel<<<dim3(16, 32), 512, S1_SMEM>>>();
    attn_wv_kernel<<<dim3(16, 32), 512, S2_SMEM>>>(attn);

    out_proj_kernel<<<dim3(8, 32, 1), 512, smem128>>>(
        (const float*)ctx, wto, bo, out);
}

// round 14
// speedup vs baseline: 1.5508x; 1.5508x over previous
#include <cuda_runtime.h>
#include <cuda_bf16.h>
#include <cstdint>

#define NB 2
#define NH 16
#define SS 2048
#define DK 64
#define DM 1024
#define NBH (NB*NH)     // 32
#define MROWS (NB*SS)   // 4096

// ---------------- scratch (allocation-free rule) ----------------
__device__ __align__(256) float g_wt[4][DM*DM];         // W^T (K-major)
__device__ __align__(256) uint16_t g_qh_h[NBH*SS*DK];   // bf16 hi [bh][s][dk]
__device__ __align__(256) uint16_t g_qh_l[NBH*SS*DK];   // bf16 lo
__device__ __align__(256) uint16_t g_kh_h[NBH*SS*DK];
__device__ __align__(256) uint16_t g_kh_l[NBH*SS*DK];
__device__ __align__(256) uint16_t g_vt_h[NBH*DK*SS];   // [bh][dk][s]
__device__ __align__(256) uint16_t g_vt_l[NBH*DK*SS];
__device__ __align__(256) float g_ctx[(size_t)MROWS*DM];
__device__ __align__(256) float2 g_stats[NBH*SS];       // (max2, sum) log2 domain

#define EP_F32 0
#define EP_QK  1
#define EP_VT  2

__device__ __forceinline__ uint32_t split2(float a, float b, uint32_t& lo) {
    __nv_bfloat162 h = __floats2bfloat162_rn(a, b);
    __nv_bfloat162 l = __floats2bfloat162_rn(a - __low2float(h), b - __high2float(h));
    lo = reinterpret_cast<uint32_t&>(l);
    return reinterpret_cast<uint32_t&>(h);
}

__device__ __forceinline__ void mma16816(float* c,
                                         uint32_t a0, uint32_t a1, uint32_t a2, uint32_t a3,
                                         uint32_t b0, uint32_t b1) {
    asm volatile(
        "mma.sync.aligned.m16n8k16.row.col.f32.bf16.bf16.f32 "
        "{%0,%1,%2,%3}, {%4,%5,%6,%7}, {%8,%9}, {%0,%1,%2,%3};"
        : "+f"(c[0]), "+f"(c[1]), "+f"(c[2]), "+f"(c[3])
        : "r"(a0), "r"(a1), "r"(a2), "r"(a3), "r"(b0), "r"(b1));
}

__device__ __forceinline__ void ldsm_x4(uint32_t& r0, uint32_t& r1,
                                        uint32_t& r2, uint32_t& r3, uint32_t a) {
    asm volatile("ldmatrix.sync.aligned.m8n8.x4.shared.b16 {%0,%1,%2,%3}, [%4];"
        : "=r"(r0), "=r"(r1), "=r"(r2), "=r"(r3) : "r"(a));
}

__device__ __forceinline__ float ex2(float x) {
    float y;
    asm("ex2.approx.f32 %0, %1;" : "=f"(y) : "f"(x));
    return y;
}

__device__ __forceinline__ void stcs2(float* p, float x, float y) {
    asm volatile("st.global.cs.v2.f32 [%0], {%1, %2};" :: "l"(p), "f"(x), "f"(y) : "memory");
}

__device__ __forceinline__ void cpa16(uint32_t dst, const void* src) {
    asm volatile("cp.async.cg.shared.global [%0], [%1], 16;" :: "r"(dst), "l"(src) : "memory");
}
#define CP_COMMIT() asm volatile("cp.async.commit_group;" ::: "memory")
#define CP_WAIT0()  asm volatile("cp.async.wait_group 0;" ::: "memory")

#define LDSTRIDE 40
#define ASZB (128 * LDSTRIDE * 2)

__device__ __forceinline__ void split_store(char* dst_h, char* dst_l, float4 v) {
    uint32_t l0, l1;
    uint32_t h0 = split2(v.x, v.y, l0);
    uint32_t h1 = split2(v.z, v.w, l1);
    *(uint2*)dst_h = make_uint2(h0, h1);
    *(uint2*)dst_l = make_uint2(l0, l1);
}

// ---------------------------------------------------------------------------
// HMMA bf16-split GEMM body (fp32 in). 256 threads, C tile 128x128, BK=32,
// double-buffered, 64x32 warp tiles (the proven R12 version).
// ---------------------------------------------------------------------------
__device__ __forceinline__ void gemm_hmma_body(
    int m0, int n0,
    const float* __restrict__ A, int lda,
    const float* __restrict__ B, int ldb, int K,
    const float* __restrict__ bias,
    float* __restrict__ out, int ldo,
    uint16_t* __restrict__ oh, uint16_t* __restrict__ ol,
    float scale, int mode, char* sm)
{
    constexpr int BN = 128, WN = 32, NI = 4, NP = 2;
    constexpr int BSZB = BN * LDSTRIDE * 2;
    constexpr int BHOFF = 2 * ASZB;
    constexpr int BUFSTR = 2 * ASZB + 2 * BSZB;

    const uint32_t smu = (uint32_t)__cvta_generic_to_shared(sm);

    const int tid  = threadIdx.x;
    const int wid  = tid >> 5;
    const int lane = tid & 31;
    const int g = lane >> 2;
    const int t = lane & 3;
    const int wm = wid & 1;
    const int wn = wid >> 1;

    const int lmat = lane >> 3;
    const int lr   = lane & 7;
    const int a_row_off = (lmat & 1) * 8 + lr;
    const int a_k_off   = (lmat >> 1) * 8;
    const int b_ni_off  = (lmat >> 1);
    const int b_k_off   = (lmat & 1) * 8;

    const int r    = tid >> 1;
    const int half = tid & 1;
    const float* Ap = A + (size_t)(m0 + r) * lda + half * 16;
    const float* Bp = B + (size_t)(n0 + r) * ldb + half * 16;

    float acc[4][NI][4];
    #pragma unroll
    for (int mi = 0; mi < 4; mi++)
        #pragma unroll
        for (int ni = 0; ni < NI; ni++)
            #pragma unroll
            for (int c = 0; c < 4; c++) acc[mi][ni][c] = 0.f;

    const int nchunk = K >> 5;

    {
        char* bh = sm + (r * LDSTRIDE + half * 16) * 2;
        #pragma unroll
        for (int j = 0; j < 4; j++)
            split_store(bh + j * 8, bh + ASZB + j * 8, *(const float4*)(Ap + j * 4));
        char* bb = sm + BHOFF + (r * LDSTRIDE + half * 16) * 2;
        #pragma unroll
        for (int j = 0; j < 4; j++)
            split_store(bb + j * 8, bb + BSZB + j * 8, *(const float4*)(Bp + j * 4));
    }
    __syncthreads();

    for (int c = 0; c < nchunk; c++) {
        const int buf = c & 1;
        const bool more = (c + 1 < nchunk);

        float4 pa[4], pb[4];
        if (more) {
            const int k0 = (c + 1) << 5;
            #pragma unroll
            for (int j = 0; j < 4; j++) pa[j] = *(const float4*)(Ap + k0 + j * 4);
            #pragma unroll
            for (int j = 0; j < 4; j++) pb[j] = *(const float4*)(Bp + k0 + j * 4);
        }

        const uint32_t base = smu + buf * BUFSTR;
        #pragma unroll
        for (int kk = 0; kk < 32; kk += 16) {
            uint32_t bfh[NI][2], bfl[NI][2];
            #pragma unroll
            for (int p = 0; p < NP; p++) {
                const int ni = p * 2 + b_ni_off;
                const int n = wn * WN + ni * 8 + lr;
                const uint32_t ab = base + BHOFF + (uint32_t)(n * LDSTRIDE + kk + b_k_off) * 2;
                ldsm_x4(bfh[p*2][0], bfh[p*2][1], bfh[p*2+1][0], bfh[p*2+1][1], ab);
                ldsm_x4(bfl[p*2][0], bfl[p*2][1], bfl[p*2+1][0], bfl[p*2+1][1], ab + BSZB);
            }
            #pragma unroll
            for (int mi = 0; mi < 4; mi++) {
                const int row = wm * 64 + mi * 16 + a_row_off;
                const uint32_t aa = base + (uint32_t)(row * LDSTRIDE + kk + a_k_off) * 2;
                uint32_t ah0, ah1, ah2, ah3, al0, al1, al2, al3;
                ldsm_x4(ah0, ah1, ah2, ah3, aa);
                ldsm_x4(al0, al1, al2, al3, aa + ASZB);
                #pragma unroll
                for (int np = 0; np < NI / 2; np++) {
                    float* c0 = acc[mi][np*2];
                    float* c1 = acc[mi][np*2+1];
                    mma16816(c0, ah0, ah1, ah2, ah3, bfh[np*2][0],   bfh[np*2][1]);
                    mma16816(c1, ah0, ah1, ah2, ah3, bfh[np*2+1][0], bfh[np*2+1][1]);
                    mma16816(c0, ah0, ah1, ah2, ah3, bfl[np*2][0],   bfl[np*2][1]);
                    mma16816(c1, ah0, ah1, ah2, ah3, bfl[np*2+1][0], bfl[np*2+1][1]);
                    mma16816(c0, al0, al1, al2, al3, bfh[np*2][0],   bfh[np*2][1]);
                    mma16816(c1, al0, al1, al2, al3, bfh[np*2+1][0], bfh[np*2+1][1]);
                }
            }
        }

        if (more) {
            __syncthreads();
            char* bh = sm + (buf ^ 1) * BUFSTR + (r * LDSTRIDE + half * 16) * 2;
            #pragma unroll
            for (int j = 0; j < 4; j++)
                split_store(bh + j * 8, bh + ASZB + j * 8, pa[j]);
            char* bb = sm + (buf ^ 1) * BUFSTR + BHOFF + (r * LDSTRIDE + half * 16) * 2;
            #pragma unroll
            for (int j = 0; j < 4; j++)
                split_store(bb + j * 8, bb + BSZB + j * 8, pb[j]);
            __syncthreads();
        }
    }

    const bool hasb = (bias != nullptr);
    #pragma unroll
    for (int mi = 0; mi < 4; mi++) {
        #pragma unroll
        for (int ni = 0; ni < NI; ni++) {
            const int row0 = m0 + wm * 64 + mi * 16 + g;
            const int row1 = row0 + 8;
            const int col  = n0 + wn * WN + ni * 8 + 2 * t;
            float b0 = hasb ? bias[col]     : 0.f;
            float b1 = hasb ? bias[col + 1] : 0.f;
            float v0 = acc[mi][ni][0] * scale + b0;
            float v1 = acc[mi][ni][1] * scale + b1;
            float v2 = acc[mi][ni][2] * scale + b0;
            float v3 = acc[mi][ni][3] * scale + b1;
            if (mode == EP_F32) {
                *(float2*)(out + (size_t)row0 * ldo + col) = make_float2(v0, v1);
                *(float2*)(out + (size_t)row1 * ldo + col) = make_float2(v2, v3);
            } else if (mode == EP_QK) {
                int h = col >> 6, dk = col & 63;
                int b_0 = row0 >> 11, s_0 = row0 & (SS - 1);
                int b_1 = row1 >> 11, s_1 = row1 & (SS - 1);
                uint32_t l01, l23;
                uint32_t h01 = split2(v0, v1, l01);
                uint32_t h23 = split2(v2, v3, l23);
                size_t i0 = ((size_t)(b_0 * NH + h) * SS + s_0) * DK + dk;
                size_t i1 = ((size_t)(b_1 * NH + h) * SS + s_1) * DK + dk;
                *(uint32_t*)(oh + i0) = h01; *(uint32_t*)(ol + i0) = l01;
                *(uint32_t*)(oh + i1) = h23; *(uint32_t*)(ol + i1) = l23;
            } else { // EP_VT: transposed singles
                int h = col >> 6, dk = col & 63;
                int b_0 = row0 >> 11, s_0 = row0 & (SS - 1);
                int b_1 = row1 >> 11, s_1 = row1 & (SS - 1);
                float vv[4] = {v0, v1, v2, v3};
                #pragma unroll
                for (int e = 0; e < 4; e++) {
                    int dkk = dk + (e & 1);
                    int ss  = (e < 2) ? s_0 : s_1;
                    int bb0 = (e < 2) ? b_0 : b_1;
                    __nv_bfloat16 hb = __float2bfloat16(vv[e]);
                    __nv_bfloat16 lb = __float2bfloat16(vv[e] - __bfloat162float(hb));
                    size_t idx = ((size_t)(bb0 * NH + h) * DK + dkk) * SS + ss;
                    oh[idx] = reinterpret_cast<uint16_t&>(hb);
                    ol[idx] = reinterpret_cast<uint16_t&>(lb);
                }
            }
        }
    }
}

__global__ void __launch_bounds__(256)
qkv_proj_kernel(const float* __restrict__ q, const float* __restrict__ k,
                const float* __restrict__ v,
                const float* __restrict__ wtq, const float* __restrict__ wtk,
                const float* __restrict__ wtv,
                const float* __restrict__ bq, const float* __restrict__ bk,
                const float* __restrict__ bv)
{
    extern __shared__ char sm[];
    const int z = blockIdx.z;
    const float* A = (z == 0) ? q : (z == 1) ? k : v;
    const float* B = (z == 0) ? wtq : (z == 1) ? wtk : wtv;
    const float* bias = (z == 0) ? bq : (z == 1) ? bk : bv;
    uint16_t* oh = (z == 0) ? g_qh_h : (z == 1) ? g_kh_h : g_vt_h;
    uint16_t* ol = (z == 0) ? g_qh_l : (z == 1) ? g_kh_l : g_vt_l;
    const int mode = (z == 2) ? EP_VT : EP_QK;
    gemm_hmma_body(blockIdx.y * 128, blockIdx.x * 128,
                   A, DM, B, DM, DM, bias, nullptr, 0, oh, ol, 1.f, mode, sm);
}

__global__ void __launch_bounds__(256)
out_proj_kernel(const float* __restrict__ A, const float* __restrict__ B,
                const float* __restrict__ bias, float* __restrict__ out)
{
    extern __shared__ char sm[];
    gemm_hmma_body(blockIdx.y * 128, blockIdx.x * 128,
                   A, DM, B, DM, DM, bias, out, DM, nullptr, nullptr, 1.f, EP_F32, sm);
}

// ===========================================================================
// Fused attention, 512 threads, cp.async double-buffered K/V.
// warp = (rowgrp 0-7, nhalf 0-1): 16 rows x 64 chunk-cols each.
// ===========================================================================
#define QSTR 144
#define VSTR 272
#define QHSZ 18432
#define VHSZ 17408
#define KOFF 36864
#define S1_BUF 36864
#define S2_BUF 71680
#define S1_SMEM (KOFF + 2*S1_BUF)
#define S2_SMEM (KOFF + 2*S2_BUF)

#define S2LOG 0.1803368801111204f  // 0.125 * log2(e)

// ---- pass 1: online softmax stats, 512 threads, N-split ----
__global__ void __launch_bounds__(512) attn_stats_kernel()
{
    extern __shared__ char sm[];
    const uint32_t smu = (uint32_t)__cvta_generic_to_shared(sm);
    const int tid = threadIdx.x;
    const int w = tid >> 5;
    const int rowgrp = w >> 1;
    const int nhalf  = w & 1;
    const int lane = tid & 31;
    const int g = lane >> 2, t = lane & 3;
    const int lmat = lane >> 3, lr = lane & 7;
    const int a_row_off = (lmat & 1) * 8 + lr;
    const int a_k_off   = (lmat >> 1) * 8;
    const int b_ni_off  = (lmat >> 1);
    const int b_k_off   = (lmat & 1) * 8;

    const int m0 = blockIdx.x * 128;
    const int bh = blockIdx.y;

    const int r  = tid >> 2, q4 = tid & 3;
    const uint16_t* Qh = g_qh_h + ((size_t)bh * SS + m0 + r) * DK + q4 * 16;
    const uint16_t* Ql = g_qh_l + ((size_t)bh * SS + m0 + r) * DK + q4 * 16;
    const uint16_t* Kh = g_kh_h + ((size_t)bh * SS + r) * DK + q4 * 16;
    const uint16_t* Kl = g_kh_l + ((size_t)bh * SS + r) * DK + q4 * 16;
    const uint32_t rowdst = (uint32_t)(r * QSTR + q4 * 32);

    cpa16(smu + rowdst,             Qh);   cpa16(smu + rowdst + 16,           Qh + 8);
    cpa16(smu + rowdst + QHSZ,      Ql);   cpa16(smu + rowdst + QHSZ + 16,    Ql + 8);
    cpa16(smu + KOFF + rowdst,      Kh);   cpa16(smu + KOFF + rowdst + 16,    Kh + 8);
    cpa16(smu + KOFF + rowdst+QHSZ, Kl);   cpa16(smu + KOFF + rowdst+QHSZ+16, Kl + 8);
    CP_COMMIT();

    uint32_t aqh[4][4], aql[4][4];
    float m[2] = {-1e30f, -1e30f}, s[2] = {0.f, 0.f};

    for (int j = 0; j < 16; j++) {
        CP_WAIT0();
        __syncthreads();
        if (j == 0) {
            #pragma unroll
            for (int kk = 0; kk < 4; kk++) {
                const int row = rowgrp * 16 + a_row_off;
                const uint32_t aa = smu + (uint32_t)(row * QSTR) + (kk * 16 + a_k_off) * 2;
                ldsm_x4(aqh[kk][0], aqh[kk][1], aqh[kk][2], aqh[kk][3], aa);
                ldsm_x4(aql[kk][0], aql[kk][1], aql[kk][2], aql[kk][3], aa + QHSZ);
            }
        }
        if (j + 1 < 16) {
            const uint32_t d = smu + KOFF + ((j + 1) & 1) * S1_BUF;
            const uint16_t* kh2 = Kh + (size_t)(j + 1) * 128 * DK;
            const uint16_t* kl2 = Kl + (size_t)(j + 1) * 128 * DK;
            cpa16(d + rowdst,          kh2); cpa16(d + rowdst + 16,          kh2 + 8);
            cpa16(d + rowdst + QHSZ,   kl2); cpa16(d + rowdst + QHSZ + 16,   kl2 + 8);
            CP_COMMIT();
        }

        const uint32_t kbase = smu + KOFF + (j & 1) * S1_BUF;
        float acc[8][4];
        #pragma unroll
        for (int ni = 0; ni < 8; ni++)
            #pragma unroll
            for (int c = 0; c < 4; c++) acc[ni][c] = 0.f;

        #pragma unroll
        for (int kk = 0; kk < 4; kk++) {
            #pragma unroll
            for (int p = 0; p < 4; p++) {
                const int ni = p * 2 + b_ni_off;
                const int n = nhalf * 64 + ni * 8 + lr;
                const uint32_t ab = kbase + (uint32_t)(n * QSTR) + (kk * 16 + b_k_off) * 2;
                uint32_t bh0, bh1, bh2, bh3, bl0, bl1, bl2, bl3;
                ldsm_x4(bh0, bh1, bh2, bh3, ab);
                ldsm_x4(bl0, bl1, bl2, bl3, ab + QHSZ);
                float* c0 = acc[p*2];
                float* c1 = acc[p*2+1];
                mma16816(c0, aqh[kk][0], aqh[kk][1], aqh[kk][2], aqh[kk][3], bh0, bh1);
                mma16816(c1, aqh[kk][0], aqh[kk][1], aqh[kk][2], aqh[kk][3], bh2, bh3);
                mma16816(c0, aqh[kk][0], aqh[kk][1], aqh[kk][2], aqh[kk][3], bl0, bl1);
                mma16816(c1, aqh[kk][0], aqh[kk][1], aqh[kk][2], aqh[kk][3], bl2, bl3);
                mma16816(c0, aql[kk][0], aql[kk][1], aql[kk][2], aql[kk][3], bh0, bh1);
                mma16816(c1, aql[kk][0], aql[kk][1], aql[kk][2], aql[kk][3], bh2, bh3);
            }
        }

        #pragma unroll
        for (int h2 = 0; h2 < 2; h2++) {
            float cm = -1e30f;
            #pragma unroll
            for (int ni = 0; ni < 8; ni++)
                cm = fmaxf(cm, fmaxf(acc[ni][h2*2], acc[ni][h2*2+1]));
            cm *= S2LOG;
            cm = fmaxf(cm, __shfl_xor_sync(0xffffffffu, cm, 1));
            cm = fmaxf(cm, __shfl_xor_sync(0xffffffffu, cm, 2));
            float mn = fmaxf(m[h2], cm);
            float sum = 0.f;
            #pragma unroll
            for (int ni = 0; ni < 8; ni++) {
                sum += ex2(fmaf(acc[ni][h2*2],   S2LOG, -mn));
                sum += ex2(fmaf(acc[ni][h2*2+1], S2LOG, -mn));
            }
            sum += __shfl_xor_sync(0xffffffffu, sum, 1);
            sum += __shfl_xor_sync(0xffffffffu, sum, 2);
            s[h2] = s[h2] * ex2(m[h2] - mn) + sum;
            m[h2] = mn;
        }
    }

    // cross-nhalf merge via smem (buffers dead now)
    __syncthreads();
    float2* red = (float2*)sm;  // [128 rows][2 halves]
    if (t == 0) {
        red[(rowgrp * 16 + g) * 2 + nhalf]       = make_float2(m[0], s[0]);
        red[(rowgrp * 16 + g + 8) * 2 + nhalf]   = make_float2(m[1], s[1]);
    }
    __syncthreads();
    if (nhalf == 0 && t == 0) {
        #pragma unroll
        for (int h2 = 0; h2 < 2; h2++) {
            const int rr = rowgrp * 16 + g + h2 * 8;
            float2 a = red[rr * 2 + 0];
            float2 b = red[rr * 2 + 1];
            float mn = fmaxf(a.x, b.x);
            float ss = a.y * ex2(a.x - mn) + b.y * ex2(b.x - mn);
            g_stats[(size_t)bh * SS + m0 + rr] = make_float2(mn, ss);
        }
    }
}

// ---- pass 2: 512 threads, weights + PV (R12 winner, unchanged) ----
__global__ void __launch_bounds__(512) attn_wv_kernel(float* __restrict__ attn)
{
    extern __shared__ char sm[];
    const uint32_t smu = (uint32_t)__cvta_generic_to_shared(sm);
    const int tid = threadIdx.x;
    const int w = tid >> 5;
    const int rowgrp = w >> 1;
    const int nhalf  = w & 1;
    const int lane = tid & 31;
    const int g = lane >> 2, t = lane & 3;
    const int lmat = lane >> 3, lr = lane & 7;
    const int a_row_off = (lmat & 1) * 8 + lr;
    const int a_k_off   = (lmat >> 1) * 8;
    const int b_ni_off  = (lmat >> 1);
    const int b_k_off   = (lmat & 1) * 8;

    const int m0 = blockIdx.x * 128;
    const int bh = blockIdx.y;
    const int bb = bh >> 4, hh = bh & 15;
    float* attn_b = attn + (size_t)bh * SS * SS;

    const int r  = tid >> 2, q4 = tid & 3;
    const uint16_t* Qh = g_qh_h + ((size_t)bh * SS + m0 + r) * DK + q4 * 16;
    const uint16_t* Ql = g_qh_l + ((size_t)bh * SS + m0 + r) * DK + q4 * 16;
    const uint16_t* Kh = g_kh_h + ((size_t)bh * SS + r) * DK + q4 * 16;
    const uint16_t* Kl = g_kh_l + ((size_t)bh * SS + r) * DK + q4 * 16;
    const uint32_t rowdst = (uint32_t)(r * QSTR + q4 * 32);

    const int vr = tid >> 3, v8 = tid & 7;
    const uint16_t* Vh = g_vt_h + ((size_t)bh * DK + vr) * SS + v8 * 16;
    const uint16_t* Vl = g_vt_l + ((size_t)bh * DK + vr) * SS + v8 * 16;
    const uint32_t vrowdst = (uint32_t)(vr * VSTR + v8 * 32);

    cpa16(smu + rowdst,             Qh);     cpa16(smu + rowdst + 16,             Qh + 8);
    cpa16(smu + rowdst + QHSZ,      Ql);     cpa16(smu + rowdst + QHSZ + 16,      Ql + 8);
    cpa16(smu + KOFF + rowdst,      Kh);     cpa16(smu + KOFF + rowdst + 16,      Kh + 8);
    cpa16(smu + KOFF + rowdst+QHSZ, Kl);     cpa16(smu + KOFF + rowdst+QHSZ+16,   Kl + 8);
    {
        const uint32_t vd = smu + KOFF + 2*QHSZ + vrowdst;
        cpa16(vd, Vh);              cpa16(vd + 16, Vh + 8);
        cpa16(vd + VHSZ, Vl);       cpa16(vd + VHSZ + 16, Vl + 8);
    }
    CP_COMMIT();

    const int row0 = m0 + rowgrp * 16 + g;
    float2 st0 = g_stats[(size_t)bh * SS + row0];
    float2 st1 = g_stats[(size_t)bh * SS + row0 + 8];
    const float mm0 = st0.x, is0 = 1.f / st0.y;
    const float mm1 = st1.x, is1 = 1.f / st1.y;

    float ctx[8][4];
    #pragma unroll
    for (int ni = 0; ni < 8; ni++)
        #pragma unroll
        for (int c = 0; c < 4; c++) ctx[ni][c] = 0.f;

    uint32_t aqh[4][4], aql[4][4];

    for (int j = 0; j < 16; j++) {
        CP_WAIT0();
        __syncthreads();
        if (j == 0) {
            #pragma unroll
            for (int kk = 0; kk < 4; kk++) {
                const int row = rowgrp * 16 + a_row_off;
                const uint32_t aa = smu + (uint32_t)(row * QSTR) + (kk * 16 + a_k_off) * 2;
                ldsm_x4(aqh[kk][0], aqh[kk][1], aqh[kk][2], aqh[kk][3], aa);
                ldsm_x4(aql[kk][0], aql[kk][1], aql[kk][2], aql[kk][3], aa + QHSZ);
            }
        }
        if (j + 1 < 16) {
            const uint32_t bb2 = smu + KOFF + ((j + 1) & 1) * S2_BUF;
            const uint16_t* kh2 = Kh + (size_t)(j + 1) * 128 * DK;
            const uint16_t* kl2 = Kl + (size_t)(j + 1) * 128 * DK;
            cpa16(bb2 + rowdst,           kh2); cpa16(bb2 + rowdst + 16,           kh2 + 8);
            cpa16(bb2 + rowdst + QHSZ,    kl2); cpa16(bb2 + rowdst + QHSZ + 16,    kl2 + 8);
            const uint32_t vd = bb2 + 2*QHSZ + vrowdst;
            const uint16_t* vh2 = Vh + (j + 1) * 128;
            const uint16_t* vl2 = Vl + (j + 1) * 128;
            cpa16(vd, vh2);         cpa16(vd + 16, vh2 + 8);
            cpa16(vd + VHSZ, vl2);  cpa16(vd + VHSZ + 16, vl2 + 8);
            CP_COMMIT();
        }

        const uint32_t kbase = smu + KOFF + (j & 1) * S2_BUF;
        const uint32_t vbase = kbase + 2*QHSZ;

        float acc[8][4];
        #pragma unroll
        for (int ni = 0; ni < 8; ni++)
            #pragma unroll
            for (int c = 0; c < 4; c++) acc[ni][c] = 0.f;

        #pragma unroll
        for (int kk = 0; kk < 4; kk++) {
            #pragma unroll
            for (int p = 0; p < 4; p++) {
                const int ni = p * 2 + b_ni_off;
                const int n = nhalf * 64 + ni * 8 + lr;
                const uint32_t ab = kbase + (uint32_t)(n * QSTR) + (kk * 16 + b_k_off) * 2;
                uint32_t bh0, bh1, bh2, bh3, bl0, bl1, bl2, bl3;
                ldsm_x4(bh0, bh1, bh2, bh3, ab);
                ldsm_x4(bl0, bl1, bl2, bl3, ab + QHSZ);
                float* c0 = acc[p*2];
                float* c1 = acc[p*2+1];
                mma16816(c0, aqh[kk][0], aqh[kk][1], aqh[kk][2], aqh[kk][3], bh0, bh1);
                mma16816(c1, aqh[kk][0], aqh[kk][1], aqh[kk][2], aqh[kk][3], bh2, bh3);
                mma16816(c0, aqh[kk][0], aqh[kk][1], aqh[kk][2], aqh[kk][3], bl0, bl1);
                mma16816(c1, aqh[kk][0], aqh[kk][1], aqh[kk][2], aqh[kk][3], bl2, bl3);
                mma16816(c0, aql[kk][0], aql[kk][1], aql[kk][2], aql[kk][3], bh0, bh1);
                mma16816(c1, aql[kk][0], aql[kk][1], aql[kk][2], aql[kk][3], bh2, bh3);
            }
        }

        #pragma unroll
        for (int ni = 0; ni < 8; ni++) {
            acc[ni][0] = ex2(fmaf(acc[ni][0], S2LOG, -mm0)) * is0;
            acc[ni][1] = ex2(fmaf(acc[ni][1], S2LOG, -mm0)) * is0;
            acc[ni][2] = ex2(fmaf(acc[ni][2], S2LOG, -mm1)) * is1;
            acc[ni][3] = ex2(fmaf(acc[ni][3], S2LOG, -mm1)) * is1;
        }

        {
            float* p0 = attn_b + (size_t)row0 * SS + j * 128 + nhalf * 64 + 2 * t;
            float* p1 = attn_b + (size_t)(row0 + 8) * SS + j * 128 + nhalf * 64 + 2 * t;
            #pragma unroll
            for (int ni = 0; ni < 8; ni++) {
                stcs2(p0 + ni * 8, acc[ni][0], acc[ni][1]);
                stcs2(p1 + ni * 8, acc[ni][2], acc[ni][3]);
            }
        }

        #pragma unroll
        for (int u = 0; u < 4; u++) {
            uint32_t al0, al1, al2, al3;
            uint32_t ah0 = split2(acc[2*u][0],   acc[2*u][1],   al0);
            uint32_t ah1 = split2(acc[2*u][2],   acc[2*u][3],   al1);
            uint32_t ah2 = split2(acc[2*u+1][0], acc[2*u+1][1], al2);
            uint32_t ah3 = split2(acc[2*u+1][2], acc[2*u+1][3], al3);
            #pragma unroll
            for (int p = 0; p < 4; p++) {
                const int nv = (p * 2 + b_ni_off) * 8 + lr;
                const uint32_t ab = vbase + (uint32_t)(nv * VSTR)
                                  + (nhalf * 64 + u * 16 + b_k_off) * 2;
                uint32_t vh0, vh1, vh2, vh3, vl0, vl1, vl2, vl3;
                ldsm_x4(vh0, vh1, vh2, vh3, ab);
                ldsm_x4(vl0, vl1, vl2, vl3, ab + VHSZ);
                float* c0 = ctx[p*2];
                float* c1 = ctx[p*2+1];
                mma16816(c0, ah0, ah1, ah2, ah3, vh0, vh1);
                mma16816(c1, ah0, ah1, ah2, ah3, vh2, vh3);
                mma16816(c0, ah0, ah1, ah2, ah3, vl0, vl1);
                mma16816(c1, ah0, ah1, ah2, ah3, vl2, vl3);
                mma16816(c0, al0, al1, al2, al3, vh0, vh1);
                mma16816(c1, al0, al1, al2, al3, vh2, vh3);
            }
        }
    }

    __syncthreads();
    float* red = (float*)sm;
    if (nhalf == 1) {
        #pragma unroll
        for (int ni = 0; ni < 8; ni++) {
            const int dk = ni * 8 + 2 * t;
            *(float2*)&red[(rowgrp * 16 + g) * 64 + dk]     = make_float2(ctx[ni][0], ctx[ni][1]);
            *(float2*)&red[(rowgrp * 16 + g + 8) * 64 + dk] = make_float2(ctx[ni][2], ctx[ni][3]);
        }
    }
    __syncthreads();
    if (nhalf == 0) {
        #pragma unroll
        for (int ni = 0; ni < 8; ni++) {
            const int dk = ni * 8 + 2 * t;
            float2 o0 = *(float2*)&red[(rowgrp * 16 + g) * 64 + dk];
            float2 o1 = *(float2*)&red[(rowgrp * 16 + g + 8) * 64 + dk];
            float* p0 = g_ctx + ((size_t)(bb * SS) + row0) * DM + hh * DK + dk;
            float* p1 = g_ctx + ((size_t)(bb * SS) + row0 + 8) * DM + hh * DK + dk;
            *(float2*)p0 = make_float2(ctx[ni][0] + o0.x, ctx[ni][1] + o0.y);
            *(float2*)p1 = make_float2(ctx[ni][2] + o1.x, ctx[ni][3] + o1.y);
        }
    }
}

// ---------------------------------------------------------------------------
__global__ void transpose4_kernel(const float* __restrict__ s0, const float* __restrict__ s1,
                                  const float* __restrict__ s2, const float* __restrict__ s3,
                                  float* __restrict__ d0, float* __restrict__ d1,
                                  float* __restrict__ d2, float* __restrict__ d3)
{
    __shared__ float tile[32][33];
    const int z = blockIdx.z;
    const float* src = (z == 0) ? s0 : (z == 1) ? s1 : (z == 2) ? s2 : s3;
    float* dst = (z == 0) ? d0 : (z == 1) ? d1 : (z == 2) ? d2 : d3;
    int bx = blockIdx.x * 32, by = blockIdx.y * 32;
    int tx = threadIdx.x, ty = threadIdx.y;
    #pragma unroll
    for (int i = 0; i < 32; i += 8)
        tile[ty + i][tx] = src[(size_t)(by + ty + i) * DM + bx + tx];
    __syncthreads();
    #pragma unroll
    for (int i = 0; i < 32; i += 8)
        dst[(size_t)(bx + ty + i) * DM + by + tx] = tile[tx][ty + i];
}

// ---------------------------------------------------------------------------
extern "C" void kernel_launch(void* const* d_in, const int* in_sizes, int n_in,
                              void* d_out, int out_size)
{
    const float* q  = (const float*)d_in[0];
    const float* k  = (const float*)d_in[1];
    const float* v  = (const float*)d_in[2];
    const float* Wq = (const float*)d_in[3];
    const float* bq = (const float*)d_in[4];
    const float* Wk = (const float*)d_in[5];
    const float* bk = (const float*)d_in[6];
    const float* Wv = (const float*)d_in[7];
    const float* bv = (const float*)d_in[8];
    const float* Wo = (const float*)d_in[9];
    const float* bo = (const float*)d_in[10];

    float* out  = (float*)d_out;
    float* attn = out + (size_t)MROWS * DM;

    void *wt, *ctx;
    cudaGetSymbolAddress(&wt,  g_wt);
    cudaGetSymbolAddress(&ctx, g_ctx);
    float* wtq = (float*)wt;
    float* wtk = wtq + (size_t)DM*DM;
    float* wtv = wtk + (size_t)DM*DM;
    float* wto = wtv + (size_t)DM*DM;

    const int smem128 = 2 * (2*ASZB + 2*128*LDSTRIDE*2);  // 81920
    cudaFuncSetAttribute(qkv_proj_kernel,
                         cudaFuncAttributeMaxDynamicSharedMemorySize, smem128);
    cudaFuncSetAttribute(out_proj_kernel,
                         cudaFuncAttributeMaxDynamicSharedMemorySize, smem128);
    cudaFuncSetAttribute(attn_stats_kernel,
                         cudaFuncAttributeMaxDynamicSharedMemorySize, S1_SMEM);
    cudaFuncSetAttribute(attn_wv_kernel,
                         cudaFuncAttributeMaxDynamicSharedMemorySize, S2_SMEM);

    transpose4_kernel<<<dim3(32, 32, 4), dim3(32, 8)>>>(Wq, Wk, Wv, Wo,
                                                        wtq, wtk, wtv, wto);

    qkv_proj_kernel<<<dim3(8, 32, 3), 256, smem128>>>(
        q, k, v, wtq, wtk, wtv, bq, bk, bv);

    attn_stats_kernel<<<dim3(16, 32), 512, S1_SMEM>>>();
    attn_wv_kernel<<<dim3(16, 32), 512, S2_SMEM>>>(attn);

    out_proj_kernel<<<dim3(8, 32, 1), 256, smem128>>>(
        (const float*)ctx, wto, bo, out);
}